// round 7
// baseline (speedup 1.0000x reference)
#include <cuda_runtime.h>
#include <cuda_fp16.h>
#include <math.h>
#include <stdint.h>

// Problem constants
#define NT   65536      // N*T rows
#define DIMS 256        // D
#define MC   512        // M codes
#define BM   128        // rows per CTA
#define CN   128        // codes per chunk
#define BK   32         // k-chunk
#define NBLK (NT / BM)  // 512 CTAs
#define PITCH 80        // smem row pitch bytes (conflict-free ldmatrix)
#define TILE (128 * PITCH)      // 10240 bytes per 128x32 fp16 tile
#define STAGE (4 * TILE)        // Ah, Al, Bh, Bl per stage
#define INV_SCALE 4.8828125e-4f // 1/2048

__device__ float g_e2[MC];
__device__ float g_x2[NT];
__device__ int   g_counts[MC];
__device__ float g_loss_partial[NBLK];
// fp16 2-way splits; lo parts pre-scaled by 2048 (exact)
__device__ __align__(16) __half g_Eh[MC * DIMS];
__device__ __align__(16) __half g_El[MC * DIMS];
__device__ __align__(16) __half g_Xh[NT * DIMS];
__device__ __align__(16) __half g_Xl[NT * DIMS];

__device__ __forceinline__ uint32_t smem_u32(const void* p) {
    uint32_t a;
    asm("{ .reg .u64 t; cvta.to.shared.u64 t, %1; cvt.u32.u64 %0, t; }"
        : "=r"(a) : "l"(p));
    return a;
}

#define LDSM4(r0, r1, r2, r3, addr) \
    asm volatile("ldmatrix.sync.aligned.m8n8.x4.shared.b16 {%0,%1,%2,%3}, [%4];" \
                 : "=r"(r0), "=r"(r1), "=r"(r2), "=r"(r3) : "r"(addr))

// fp32-accumulate (hh product)
#define MMA_F32(d, a0, a1, a2, a3, b0, b1) \
    asm volatile("mma.sync.aligned.m16n8k16.row.col.f32.f16.f16.f32 " \
                 "{%0,%1,%2,%3}, {%4,%5,%6,%7}, {%8,%9}, {%0,%1,%2,%3};" \
                 : "+f"((d)[0]), "+f"((d)[1]), "+f"((d)[2]), "+f"((d)[3]) \
                 : "r"(a0), "r"(a1), "r"(a2), "r"(a3), "r"(b0), "r"(b1))

// fp16-accumulate (hl + lh products, scaled by 2048)
#define MMA_F16(d, a0, a1, a2, a3, b0, b1) \
    asm volatile("mma.sync.aligned.m16n8k16.row.col.f16.f16.f16.f16 " \
                 "{%0,%1}, {%2,%3,%4,%5}, {%6,%7}, {%0,%1};" \
                 : "+r"((d)[0]), "+r"((d)[1]) \
                 : "r"(a0), "r"(a1), "r"(a2), "r"(a3), "r"(b0), "r"(b1))

#define CP_ASYNC16(dst, src) \
    asm volatile("cp.async.cg.shared.global [%0], [%1], 16;" \
                 :: "r"(dst), "l"(src) : "memory")
#define CP_COMMIT() asm volatile("cp.async.commit_group;" ::: "memory")
#define CP_WAIT(n)  asm volatile("cp.async.wait_group %0;" :: "n"(n) : "memory")

// ---------------------------------------------------------------------------
// Kernel 1: row-normalize codebook exactly like the reference; fp16 splits
// (lo scaled x2048); e2 (double-accumulated, rounded once); zero counters.
// ---------------------------------------------------------------------------
__global__ void vq_normalize(const float* __restrict__ emb) {
    __shared__ double red[8];
    __shared__ float bcast;
    int m = blockIdx.x;
    int t = threadIdx.x;       // 256 = D
    float v = emb[m * DIMS + t];

    double s = (double)v * (double)v;
    #pragma unroll
    for (int o = 16; o; o >>= 1) s += __shfl_xor_sync(0xffffffffu, s, o);
    if ((t & 31) == 0) red[t >> 5] = s;
    __syncthreads();
    if (t == 0) {
        double tot = 0.0;
        #pragma unroll
        for (int i = 0; i < 8; i++) tot += red[i];
        bcast = (float)sqrt(tot);
    }
    __syncthreads();
    float norm = bcast;
    float e = v / (norm + 1e-4f);          // IEEE rn division, matches ref

    __half h = __float2half_rn(e);
    float r1 = e - __half2float(h);
    g_Eh[m * DIMS + t] = h;
    g_El[m * DIMS + t] = __float2half_rn(r1 * 2048.0f);

    __syncthreads();
    double s2 = (double)e * (double)e;
    #pragma unroll
    for (int o = 16; o; o >>= 1) s2 += __shfl_xor_sync(0xffffffffu, s2, o);
    if ((t & 31) == 0) red[t >> 5] = s2;
    __syncthreads();
    if (t == 0) {
        double tot2 = 0.0;
        #pragma unroll
        for (int i = 0; i < 8; i++) tot2 += red[i];
        g_e2[m] = (float)tot2;
        g_counts[m] = 0;
    }
}

// ---------------------------------------------------------------------------
// Kernel 1b: per-row ||x||^2 (double, rounded once) + fp16 split of x
// (lo scaled x2048). One warp per row.
// ---------------------------------------------------------------------------
__global__ void vq_prep_x(const float* __restrict__ x) {
    int warp = (blockIdx.x * blockDim.x + threadIdx.x) >> 5;
    int lane = threadIdx.x & 31;
    if (warp >= NT) return;
    const float* row = x + (size_t)warp * DIMS + lane * 8;
    float4 f0 = *(const float4*)row;
    float4 f1 = *(const float4*)(row + 4);
    float f[8] = {f0.x, f0.y, f0.z, f0.w, f1.x, f1.y, f1.z, f1.w};

    double s = 0.0;
    __half h[8], l[8];
    #pragma unroll
    for (int i = 0; i < 8; i++) {
        s += (double)f[i] * (double)f[i];
        h[i] = __float2half_rn(f[i]);
        float r = f[i] - __half2float(h[i]);
        l[i] = __float2half_rn(r * 2048.0f);
    }
    union { __half2 h2[4]; uint4 u; } P;
    size_t gi = (size_t)warp * DIMS + lane * 8;
    #pragma unroll
    for (int i = 0; i < 4; i++) P.h2[i] = __halves2half2(h[2*i], h[2*i+1]);
    *(uint4*)(g_Xh + gi) = P.u;
    #pragma unroll
    for (int i = 0; i < 4; i++) P.h2[i] = __halves2half2(l[2*i], l[2*i+1]);
    *(uint4*)(g_Xl + gi) = P.u;

    #pragma unroll
    for (int o = 16; o; o >>= 1) s += __shfl_xor_sync(0xffffffffu, s, o);
    if (lane == 0) g_x2[warp] = (float)s;
}

// ---------------------------------------------------------------------------
// Kernel 2: main. hh product -> fp32 acc; hl+lh (x2048) -> shared fp16 acc.
// Per-nc epilogue: shfl-reduce + packed smem atomicMin argmin with
// reference-identical fp32 distance rounding.
// ---------------------------------------------------------------------------
__global__ void __launch_bounds__(256, 2)
vq_main(const float* __restrict__ x, const float* __restrict__ emb,
        float* __restrict__ out) {
    extern __shared__ char dsm[];           // 2 * STAGE = 81920 bytes
    __shared__ unsigned long long s_key[BM];
    __shared__ int   s_idx[BM];
    __shared__ float s_e2[MC];
    __shared__ float s_x2[BM];
    __shared__ float sred[8];

    const int tid  = threadIdx.x;
    const int lane = tid & 31;
    const int w    = tid >> 5;
    const int wr   = w >> 2;                 // 0..1 (row block of 64)
    const int wc   = w & 3;                  // 0..3 (col block of 32)
    const int row0 = blockIdx.x * BM;

    if (tid < BM) {
        s_key[tid] = 0xFFFFFFFFFFFFFFFFULL;
        s_x2[tid] = g_x2[row0 + tid];
    }
    s_e2[tid]       = g_e2[tid];
    s_e2[tid + 256] = g_e2[tid + 256];

    // cp.async task mapping: thread covers 2 chunks per tile
    const int c0 = tid, c1 = tid + 256;
    const int r_0 = c0 >> 2, cg0 = c0 & 3;
    const int r_1 = c1 >> 2, cg1 = c1 & 3;

    auto issue_stage = [&](int ncc, int kcc, int buf) {
        uint32_t st = smem_u32(dsm) + buf * STAGE;
        size_t ka = (size_t)kcc * BK;
        const __half* srcAh = g_Xh + (size_t)(row0) * DIMS + ka;
        const __half* srcAl = g_Xl + (size_t)(row0) * DIMS + ka;
        const __half* srcBh = g_Eh + (size_t)(ncc * CN) * DIMS + ka;
        const __half* srcBl = g_El + (size_t)(ncc * CN) * DIMS + ka;
        uint32_t d0 = (uint32_t)(r_0 * PITCH + cg0 * 16);
        uint32_t d1 = (uint32_t)(r_1 * PITCH + cg1 * 16);
        size_t s0 = (size_t)r_0 * DIMS + cg0 * 8;
        size_t s1 = (size_t)r_1 * DIMS + cg1 * 8;
        CP_ASYNC16(st + d0,            srcAh + s0);
        CP_ASYNC16(st + d1,            srcAh + s1);
        CP_ASYNC16(st + TILE + d0,     srcAl + s0);
        CP_ASYNC16(st + TILE + d1,     srcAl + s1);
        CP_ASYNC16(st + 2 * TILE + d0, srcBh + s0);
        CP_ASYNC16(st + 2 * TILE + d1, srcBh + s1);
        CP_ASYNC16(st + 3 * TILE + d0, srcBl + s0);
        CP_ASYNC16(st + 3 * TILE + d1, srcBl + s1);
        CP_COMMIT();
    };

    issue_stage(0, 0, 0);

    #pragma unroll 1
    for (int nc = 0; nc < MC / CN; ++nc) {
        float    acc32[4][4][4];
        uint32_t acc16[4][4][2];
        #pragma unroll
        for (int i = 0; i < 4; i++)
            #pragma unroll
            for (int j = 0; j < 4; j++) {
                #pragma unroll
                for (int c = 0; c < 4; c++) acc32[i][j][c] = 0.f;
                acc16[i][j][0] = 0u; acc16[i][j][1] = 0u;
            }

        #pragma unroll 1
        for (int kc = 0; kc < DIMS / BK; ++kc) {
            int step = nc * 8 + kc;
            int buf = step & 1;
            if (step < 31) {
                int ns = step + 1;
                issue_stage(ns >> 3, ns & 7, ns & 1);
                CP_WAIT(1);
            } else {
                CP_WAIT(0);
            }
            __syncthreads();

            uint32_t st = smem_u32(dsm) + buf * STAGE;
            uint32_t aH = st, aL = st + TILE;
            uint32_t bH = st + 2 * TILE, bL = st + 3 * TILE;

            #pragma unroll
            for (int ks = 0; ks < 2; ++ks) {
                uint32_t lsw = (lane & 15) * PITCH + ks * 32 + (lane >> 4) * 16;
                uint32_t bOff0 = (wc * 32) * PITCH + lsw;
                uint32_t bOff1 = (wc * 32 + 16) * PITCH + lsw;

                uint32_t bh0, bh1, bh2, bh3, bh4, bh5, bh6, bh7;
                LDSM4(bh0, bh1, bh2, bh3, bH + bOff0);
                LDSM4(bh4, bh5, bh6, bh7, bH + bOff1);
                uint32_t bl0, bl1, bl2, bl3, bl4, bl5, bl6, bl7;
                LDSM4(bl0, bl1, bl2, bl3, bL + bOff0);
                LDSM4(bl4, bl5, bl6, bl7, bL + bOff1);

                #pragma unroll
                for (int i = 0; i < 4; ++i) {
                    uint32_t a0, a1, a2, a3;
                    LDSM4(a0, a1, a2, a3, aH + (wr * 64 + i * 16) * PITCH + lsw);
                    // hh -> fp32 acc
                    MMA_F32(acc32[i][0], a0, a1, a2, a3, bh0, bh2);
                    MMA_F32(acc32[i][1], a0, a1, a2, a3, bh1, bh3);
                    MMA_F32(acc32[i][2], a0, a1, a2, a3, bh4, bh6);
                    MMA_F32(acc32[i][3], a0, a1, a2, a3, bh5, bh7);
                    // hl -> fp16 acc (scaled)
                    MMA_F16(acc16[i][0], a0, a1, a2, a3, bl0, bl2);
                    MMA_F16(acc16[i][1], a0, a1, a2, a3, bl1, bl3);
                    MMA_F16(acc16[i][2], a0, a1, a2, a3, bl4, bl6);
                    MMA_F16(acc16[i][3], a0, a1, a2, a3, bl5, bl7);
                    // lh -> same fp16 acc (same 2048 scale)
                    LDSM4(a0, a1, a2, a3, aL + (wr * 64 + i * 16) * PITCH + lsw);
                    MMA_F16(acc16[i][0], a0, a1, a2, a3, bh0, bh2);
                    MMA_F16(acc16[i][1], a0, a1, a2, a3, bh1, bh3);
                    MMA_F16(acc16[i][2], a0, a1, a2, a3, bh4, bh6);
                    MMA_F16(acc16[i][3], a0, a1, a2, a3, bh5, bh7);
                }
            }
            __syncthreads();
        }

        // ---- per-nc epilogue: distance (reference rounding) + argmin
        #pragma unroll
        for (int i = 0; i < 4; ++i) {
            #pragma unroll
            for (int h = 0; h < 2; ++h) {
                int row = wr * 64 + i * 16 + (lane >> 2) + 8 * h;
                float x2v = s_x2[row];
                unsigned long long kmin = 0xFFFFFFFFFFFFFFFFULL;
                #pragma unroll
                for (int j = 0; j < 4; ++j) {
                    __half2 sm = *(__half2*)&acc16[i][j][h];
                    float s0 = __low2float(sm), s1 = __high2float(sm);
                    #pragma unroll
                    for (int cl = 0; cl < 2; ++cl) {
                        int c = nc * CN + wc * 32 + j * 8 + 2 * (lane & 3) + cl;
                        float dot = __fmaf_rn(cl ? s1 : s0, INV_SCALE,
                                              acc32[i][j][2 * h + cl]);
                        float base = __fadd_rn(s_e2[c], x2v);
                        float dval = __fmaf_rn(-2.0f, dot, base);
                        uint32_t u = __float_as_uint(dval);
                        uint32_t k = (u & 0x80000000u) ? ~u : (u | 0x80000000u);
                        unsigned long long key =
                            ((unsigned long long)k << 32) | (uint32_t)c;
                        if (key < kmin) kmin = key;
                    }
                }
                // reduce over the 4 lanes sharing this row (lane^1, lane^2)
                unsigned long long o1 = __shfl_xor_sync(0xffffffffu, kmin, 1);
                if (o1 < kmin) kmin = o1;
                unsigned long long o2 = __shfl_xor_sync(0xffffffffu, kmin, 2);
                if (o2 < kmin) kmin = o2;
                if ((lane & 3) == 0) atomicMin(&s_key[row], kmin);
            }
        }
    }
    __syncthreads();

    if (tid < BM) {
        int bi = (int)(uint32_t)s_key[tid];
        s_idx[tid] = bi;
        atomicAdd(&g_counts[bi], 1);
    }
    __syncthreads();

    // ---- gather raw embedding rows, write out, commitment partial
    float lsum = 0.f;
    #pragma unroll 4
    for (int r = 0; r < BM; r++) {
        int ci = s_idx[r];
        float qv = emb[(size_t)ci * DIMS + tid];
        float xv = x[(size_t)(row0 + r) * DIMS + tid];
        out[(size_t)(row0 + r) * DIMS + tid] = qv;
        float d = xv - qv;
        lsum = fmaf(d, d, lsum);
    }
    #pragma unroll
    for (int o = 16; o; o >>= 1) lsum += __shfl_xor_sync(0xffffffffu, lsum, o);
    if ((tid & 31) == 0) sred[tid >> 5] = lsum;
    __syncthreads();
    if (tid == 0) {
        float s = 0.f;
        #pragma unroll
        for (int i = 0; i < 8; i++) s += sred[i];
        g_loss_partial[blockIdx.x] = s;
    }
}

// ---------------------------------------------------------------------------
// Kernel 3: finalize scalars.
// ---------------------------------------------------------------------------
__global__ void vq_finalize(float* __restrict__ out) {
    __shared__ float sE[16], sL[16];
    int t = threadIdx.x;  // 512
    float p  = (float)g_counts[t] * (1.0f / 65536.0f);
    float ent = p * logf(p + 1e-10f);
    float lp  = g_loss_partial[t];
    #pragma unroll
    for (int o = 16; o; o >>= 1) {
        ent += __shfl_xor_sync(0xffffffffu, ent, o);
        lp  += __shfl_xor_sync(0xffffffffu, lp, o);
    }
    if ((t & 31) == 0) { sE[t >> 5] = ent; sL[t >> 5] = lp; }
    __syncthreads();
    if (t == 0) {
        float e = 0.f, l = 0.f;
        #pragma unroll
        for (int i = 0; i < 16; i++) { e += sE[i]; l += sL[i]; }
        out[(size_t)NT * DIMS]     = l * (1.0f / 16777216.0f);
        out[(size_t)NT * DIMS + 1] = expf(-e);
    }
}

extern "C" void kernel_launch(void* const* d_in, const int* in_sizes, int n_in,
                              void* d_out, int out_size) {
    const float* x   = (const float*)d_in[0];   // (16,4096,256)
    const float* emb = (const float*)d_in[1];   // (512,256)
    float* out = (float*)d_out;

    static int attr_done = 0;
    const int DSMEM = 2 * STAGE;                // 81920 bytes
    if (!attr_done) {
        cudaFuncSetAttribute(vq_main, cudaFuncAttributeMaxDynamicSharedMemorySize, DSMEM);
        attr_done = 1;
    }

    vq_normalize<<<MC, DIMS>>>(emb);
    vq_prep_x<<<NT / 8, 256>>>(x);              // 8 warps/block, 1 warp/row
    vq_main<<<NBLK, 256, DSMEM>>>(x, emb, out);
    vq_finalize<<<1, MC>>>(out);
}

// round 9
// speedup vs baseline: 1.0168x; 1.0168x over previous
#include <cuda_runtime.h>
#include <cuda_fp16.h>
#include <math.h>
#include <stdint.h>

// Problem constants
#define NT   65536      // N*T rows
#define DIMS 256        // D
#define MC   512        // M codes
#define BM   128        // rows per CTA
#define CN   128        // codes per chunk
#define BK   32         // k-chunk
#define NBLK (NT / BM)  // 512 CTAs
#define PITCH 80        // smem row pitch bytes (conflict-free ldmatrix)
#define TILE (128 * PITCH)      // 10240 bytes per 128x32 fp16 tile
#define STAGE2 (2 * TILE)       // Ah, Bh per stage
#define CAP  32                 // candidate slots per row

__device__ float g_e2[MC];
__device__ float g_x2[NT];
__device__ int   g_counts[MC];
__device__ float g_loss_partial[NBLK];
__device__ __align__(16) __half g_Eh[MC * DIMS];   // fp16 hi of emb_norm
__device__ __align__(16) float  g_En[MC * DIMS];   // fp32 emb_norm (refine)
__device__ __align__(16) __half g_Xh[NT * DIMS];   // fp16 hi of x

__device__ __forceinline__ uint32_t smem_u32(const void* p) {
    uint32_t a;
    asm("{ .reg .u64 t; cvta.to.shared.u64 t, %1; cvt.u32.u64 %0, t; }"
        : "=r"(a) : "l"(p));
    return a;
}
__device__ __forceinline__ uint32_t enc_f(float f) {
    uint32_t u = __float_as_uint(f);
    return (u & 0x80000000u) ? ~u : (u | 0x80000000u);
}
__device__ __forceinline__ float dec_f(uint32_t k) {
    uint32_t u = (k & 0x80000000u) ? (k & 0x7FFFFFFFu) : ~k;
    return __uint_as_float(u);
}

#define LDSM4(r0, r1, r2, r3, addr) \
    asm volatile("ldmatrix.sync.aligned.m8n8.x4.shared.b16 {%0,%1,%2,%3}, [%4];" \
                 : "=r"(r0), "=r"(r1), "=r"(r2), "=r"(r3) : "r"(addr))

#define MMA_F32(d, a0, a1, a2, a3, b0, b1) \
    asm volatile("mma.sync.aligned.m16n8k16.row.col.f32.f16.f16.f32 " \
                 "{%0,%1,%2,%3}, {%4,%5,%6,%7}, {%8,%9}, {%0,%1,%2,%3};" \
                 : "+f"((d)[0]), "+f"((d)[1]), "+f"((d)[2]), "+f"((d)[3]) \
                 : "r"(a0), "r"(a1), "r"(a2), "r"(a3), "r"(b0), "r"(b1))

#define CP_ASYNC16(dst, src) \
    asm volatile("cp.async.cg.shared.global [%0], [%1], 16;" \
                 :: "r"(dst), "l"(src) : "memory")
#define CP_COMMIT() asm volatile("cp.async.commit_group;" ::: "memory")
#define CP_WAIT(n)  asm volatile("cp.async.wait_group %0;" :: "n"(n) : "memory")

// ---------------------------------------------------------------------------
// Kernel 1: row-normalize codebook exactly like the reference; emit fp16 hi
// split + fp32 copy; e2 (double-accumulated, rounded once); zero counters.
// ---------------------------------------------------------------------------
__global__ void vq_normalize(const float* __restrict__ emb) {
    __shared__ double red[8];
    __shared__ float bcast;
    int m = blockIdx.x;
    int t = threadIdx.x;       // 256 = D
    float v = emb[m * DIMS + t];

    double s = (double)v * (double)v;
    #pragma unroll
    for (int o = 16; o; o >>= 1) s += __shfl_xor_sync(0xffffffffu, s, o);
    if ((t & 31) == 0) red[t >> 5] = s;
    __syncthreads();
    if (t == 0) {
        double tot = 0.0;
        #pragma unroll
        for (int i = 0; i < 8; i++) tot += red[i];
        bcast = (float)sqrt(tot);
    }
    __syncthreads();
    float norm = bcast;
    float e = v / (norm + 1e-4f);          // IEEE rn division, matches ref

    g_Eh[m * DIMS + t] = __float2half_rn(e);
    g_En[m * DIMS + t] = e;

    __syncthreads();
    double s2 = (double)e * (double)e;
    #pragma unroll
    for (int o = 16; o; o >>= 1) s2 += __shfl_xor_sync(0xffffffffu, s2, o);
    if ((t & 31) == 0) red[t >> 5] = s2;
    __syncthreads();
    if (t == 0) {
        double tot2 = 0.0;
        #pragma unroll
        for (int i = 0; i < 8; i++) tot2 += red[i];
        g_e2[m] = (float)tot2;
        g_counts[m] = 0;
    }
}

// ---------------------------------------------------------------------------
// Kernel 1b: per-row ||x||^2 (double, rounded once) + fp16 hi split of x.
// ---------------------------------------------------------------------------
__global__ void vq_prep_x(const float* __restrict__ x) {
    int warp = (blockIdx.x * blockDim.x + threadIdx.x) >> 5;
    int lane = threadIdx.x & 31;
    if (warp >= NT) return;
    const float* row = x + (size_t)warp * DIMS + lane * 8;
    float4 f0 = *(const float4*)row;
    float4 f1 = *(const float4*)(row + 4);
    float f[8] = {f0.x, f0.y, f0.z, f0.w, f1.x, f1.y, f1.z, f1.w};

    double s = 0.0;
    __half h[8];
    #pragma unroll
    for (int i = 0; i < 8; i++) {
        s += (double)f[i] * (double)f[i];
        h[i] = __float2half_rn(f[i]);
    }
    union { __half2 h2[4]; uint4 u; } P;
    #pragma unroll
    for (int i = 0; i < 4; i++) P.h2[i] = __halves2half2(h[2*i], h[2*i+1]);
    *(uint4*)(g_Xh + (size_t)warp * DIMS + lane * 8) = P.u;

    #pragma unroll
    for (int o = 16; o; o >>= 1) s += __shfl_xor_sync(0xffffffffu, s, o);
    if (lane == 0) g_x2[warp] = (float)s;
}

// ---------------------------------------------------------------------------
// Kernel 2: main. hh-only MMA sweep with running-min + margin candidate
// collection, then exact fp32 candidate refinement (reference-identical
// rounding, lower-index ties). Refine loop is warp-uniform (fixed R8 crash).
// ---------------------------------------------------------------------------
__global__ void __launch_bounds__(256, 2)
vq_main(const float* __restrict__ x, const float* __restrict__ emb,
        float* __restrict__ out) {
    extern __shared__ char dsm[];           // 2 * STAGE2 = 40960 bytes
    __shared__ unsigned long long s_key[BM];
    __shared__ int      s_idx[BM];
    __shared__ int      s_cnt[BM];
    __shared__ uint16_t s_cand[BM][CAP];
    __shared__ float    s_e2[MC];
    __shared__ float    s_x2[BM];
    __shared__ float    s_mrg[BM];
    __shared__ float    sred[8];

    const int tid  = threadIdx.x;
    const int lane = tid & 31;
    const int w    = tid >> 5;
    const int wr   = w >> 2;                 // 0..1 (row block of 64)
    const int wc   = w & 3;                  // 0..3 (col block of 32)
    const int row0 = blockIdx.x * BM;

    if (tid < BM) {
        s_key[tid] = 0xFFFFFFFFFFFFFFFFULL;
        s_cnt[tid] = 0;
        float x2v = g_x2[row0 + tid];
        s_x2[tid] = x2v;
        s_mrg[tid] = __fmaf_rn(0.004f, sqrtf(x2v), 0.01f);  // rigorous + safety
    }
    s_e2[tid]       = g_e2[tid];
    s_e2[tid + 256] = g_e2[tid + 256];

    // cp.async task mapping: thread covers 2 chunks per tile
    const int c0 = tid, c1 = tid + 256;
    const int r_0 = c0 >> 2, cg0 = c0 & 3;
    const int r_1 = c1 >> 2, cg1 = c1 & 3;

    auto issue_stage = [&](int ncc, int kcc, int buf) {
        uint32_t st = smem_u32(dsm) + buf * STAGE2;
        size_t ka = (size_t)kcc * BK;
        const __half* srcA = g_Xh + (size_t)(row0) * DIMS + ka;
        const __half* srcB = g_Eh + (size_t)(ncc * CN) * DIMS + ka;
        uint32_t d0 = (uint32_t)(r_0 * PITCH + cg0 * 16);
        uint32_t d1 = (uint32_t)(r_1 * PITCH + cg1 * 16);
        size_t s0 = (size_t)r_0 * DIMS + cg0 * 8;
        size_t s1 = (size_t)r_1 * DIMS + cg1 * 8;
        CP_ASYNC16(st + d0,        srcA + s0);
        CP_ASYNC16(st + d1,        srcA + s1);
        CP_ASYNC16(st + TILE + d0, srcB + s0);
        CP_ASYNC16(st + TILE + d1, srcB + s1);
        CP_COMMIT();
    };

    issue_stage(0, 0, 0);

    #pragma unroll 1
    for (int nc = 0; nc < MC / CN; ++nc) {
        float acc[4][4][4];
        #pragma unroll
        for (int i = 0; i < 4; i++)
            #pragma unroll
            for (int j = 0; j < 4; j++)
                #pragma unroll
                for (int c = 0; c < 4; c++) acc[i][j][c] = 0.f;

        #pragma unroll 1
        for (int kc = 0; kc < DIMS / BK; ++kc) {
            int step = nc * 8 + kc;
            int buf = step & 1;
            if (step < 31) {
                int ns = step + 1;
                issue_stage(ns >> 3, ns & 7, ns & 1);
                CP_WAIT(1);
            } else {
                CP_WAIT(0);
            }
            __syncthreads();

            uint32_t st = smem_u32(dsm) + buf * STAGE2;
            uint32_t aH = st, bH = st + TILE;

            #pragma unroll
            for (int ks = 0; ks < 2; ++ks) {
                uint32_t lsw = (lane & 15) * PITCH + ks * 32 + (lane >> 4) * 16;
                uint32_t b0, b1, b2, b3, b4, b5, b6, b7;
                LDSM4(b0, b1, b2, b3, bH + (wc * 32)      * PITCH + lsw);
                LDSM4(b4, b5, b6, b7, bH + (wc * 32 + 16) * PITCH + lsw);
                #pragma unroll
                for (int i = 0; i < 4; ++i) {
                    uint32_t a0, a1, a2, a3;
                    LDSM4(a0, a1, a2, a3, aH + (wr * 64 + i * 16) * PITCH + lsw);
                    MMA_F32(acc[i][0], a0, a1, a2, a3, b0, b2);
                    MMA_F32(acc[i][1], a0, a1, a2, a3, b1, b3);
                    MMA_F32(acc[i][2], a0, a1, a2, a3, b4, b6);
                    MMA_F32(acc[i][3], a0, a1, a2, a3, b5, b7);
                }
            }
            __syncthreads();
        }

        // ---- phase 1: update per-row running min with this chunk
        #pragma unroll
        for (int i = 0; i < 4; ++i) {
            #pragma unroll
            for (int h = 0; h < 2; ++h) {
                int row = wr * 64 + i * 16 + (lane >> 2) + 8 * h;
                float x2v = s_x2[row];
                unsigned long long kmin = 0xFFFFFFFFFFFFFFFFULL;
                #pragma unroll
                for (int j = 0; j < 4; ++j) {
                    #pragma unroll
                    for (int cl = 0; cl < 2; ++cl) {
                        int c = nc * CN + wc * 32 + j * 8 + 2 * (lane & 3) + cl;
                        float base = __fadd_rn(s_e2[c], x2v);
                        float dval = __fmaf_rn(-2.0f, acc[i][j][2 * h + cl], base);
                        unsigned long long key =
                            ((unsigned long long)enc_f(dval) << 32) | (uint32_t)c;
                        if (key < kmin) kmin = key;
                    }
                }
                unsigned long long o1 = __shfl_xor_sync(0xffffffffu, kmin, 1);
                if (o1 < kmin) kmin = o1;
                unsigned long long o2 = __shfl_xor_sync(0xffffffffu, kmin, 2);
                if (o2 < kmin) kmin = o2;
                if ((lane & 3) == 0) atomicMin(&s_key[row], kmin);
            }
        }
        __syncthreads();

        // ---- phase 2: collect candidates within margin of the running min
        #pragma unroll
        for (int i = 0; i < 4; ++i) {
            #pragma unroll
            for (int h = 0; h < 2; ++h) {
                int row = wr * 64 + i * 16 + (lane >> 2) + 8 * h;
                float x2v = s_x2[row];
                float thr = dec_f((uint32_t)(s_key[row] >> 32)) + s_mrg[row];
                #pragma unroll
                for (int j = 0; j < 4; ++j) {
                    #pragma unroll
                    for (int cl = 0; cl < 2; ++cl) {
                        int c = nc * CN + wc * 32 + j * 8 + 2 * (lane & 3) + cl;
                        float base = __fadd_rn(s_e2[c], x2v);
                        float dval = __fmaf_rn(-2.0f, acc[i][j][2 * h + cl], base);
                        if (dval < thr) {
                            int p = atomicAdd(&s_cnt[row], 1);
                            if (p < CAP) s_cand[row][p] = (uint16_t)c;
                        }
                    }
                }
            }
        }
        __syncthreads();
    }

    // ---- refinement: exact fp32 dot for candidates; one warp per row.
    // WARP-UNIFORM loop: all 32 lanes run ceil(n/4) iterations; invalid
    // slots clamp to candidate 0 and are predicated out of the key update.
    {
        const int gl = lane >> 3;   // group 0..3
        const int gi = lane & 7;    // lane within group
        #pragma unroll 1
        for (int rr = w; rr < BM; rr += 8) {
            int n = s_cnt[rr];
            bool ovf = (n > CAP);
            if (ovf) n = MC;
            float x2v = s_x2[rr];
            const float* xr = x + (size_t)(row0 + rr) * DIMS + gi * 32;
            float4 xv[8];
            #pragma unroll
            for (int q = 0; q < 8; q++) xv[q] = *(const float4*)(xr + 4 * q);

            unsigned long long best = 0xFFFFFFFFFFFFFFFFULL;
            int nIter = (n + 3) >> 2;          // uniform across the warp
            #pragma unroll 1
            for (int ii = 0; ii < nIter; ++ii) {
                int t = ii * 4 + gl;
                bool valid = (t < n);
                int ts = valid ? t : 0;        // n >= 1 always
                int c = ovf ? ts : (int)s_cand[rr][ts];
                const float* er = g_En + (size_t)c * DIMS + gi * 32;
                float dot = 0.f;
                #pragma unroll
                for (int q = 0; q < 8; q++) {
                    float4 ev = *(const float4*)(er + 4 * q);
                    dot = fmaf(xv[q].x, ev.x, dot);
                    dot = fmaf(xv[q].y, ev.y, dot);
                    dot = fmaf(xv[q].z, ev.z, dot);
                    dot = fmaf(xv[q].w, ev.w, dot);
                }
                dot += __shfl_xor_sync(0xffffffffu, dot, 1);
                dot += __shfl_xor_sync(0xffffffffu, dot, 2);
                dot += __shfl_xor_sync(0xffffffffu, dot, 4);
                if (gi == 0 && valid) {
                    float base = __fadd_rn(s_e2[c], x2v);
                    float dval = __fmaf_rn(-2.0f, dot, base);
                    unsigned long long key =
                        ((unsigned long long)enc_f(dval) << 32) | (uint32_t)c;
                    if (key < best) best = key;
                }
            }
            // warp-wide min (non-leader lanes hold ~0 = max)
            #pragma unroll
            for (int o = 1; o < 32; o <<= 1) {
                unsigned long long ok = __shfl_xor_sync(0xffffffffu, best, o);
                if (ok < best) best = ok;
            }
            if (lane == 0) {
                int bi = (int)(uint32_t)best;
                s_idx[rr] = bi;
                atomicAdd(&g_counts[bi], 1);
            }
        }
    }
    __syncthreads();

    // ---- gather raw embedding rows, write out, commitment partial
    float lsum = 0.f;
    #pragma unroll 4
    for (int r = 0; r < BM; r++) {
        int ci = s_idx[r];
        float qv = emb[(size_t)ci * DIMS + tid];
        float xv = x[(size_t)(row0 + r) * DIMS + tid];
        out[(size_t)(row0 + r) * DIMS + tid] = qv;
        float d = xv - qv;
        lsum = fmaf(d, d, lsum);
    }
    #pragma unroll
    for (int o = 16; o; o >>= 1) lsum += __shfl_xor_sync(0xffffffffu, lsum, o);
    if ((tid & 31) == 0) sred[tid >> 5] = lsum;
    __syncthreads();
    if (tid == 0) {
        float s = 0.f;
        #pragma unroll
        for (int i = 0; i < 8; i++) s += sred[i];
        g_loss_partial[blockIdx.x] = s;
    }
}

// ---------------------------------------------------------------------------
// Kernel 3: finalize scalars.
// ---------------------------------------------------------------------------
__global__ void vq_finalize(float* __restrict__ out) {
    __shared__ float sE[16], sL[16];
    int t = threadIdx.x;  // 512
    float p  = (float)g_counts[t] * (1.0f / 65536.0f);
    float ent = p * logf(p + 1e-10f);
    float lp  = g_loss_partial[t];
    #pragma unroll
    for (int o = 16; o; o >>= 1) {
        ent += __shfl_xor_sync(0xffffffffu, ent, o);
        lp  += __shfl_xor_sync(0xffffffffu, lp, o);
    }
    if ((t & 31) == 0) { sE[t >> 5] = ent; sL[t >> 5] = lp; }
    __syncthreads();
    if (t == 0) {
        float e = 0.f, l = 0.f;
        #pragma unroll
        for (int i = 0; i < 16; i++) { e += sE[i]; l += sL[i]; }
        out[(size_t)NT * DIMS]     = l * (1.0f / 16777216.0f);
        out[(size_t)NT * DIMS + 1] = expf(-e);
    }
}

extern "C" void kernel_launch(void* const* d_in, const int* in_sizes, int n_in,
                              void* d_out, int out_size) {
    const float* x   = (const float*)d_in[0];   // (16,4096,256)
    const float* emb = (const float*)d_in[1];   // (512,256)
    float* out = (float*)d_out;

    static int attr_done = 0;
    const int DSMEM = 2 * STAGE2;               // 40960 bytes
    if (!attr_done) {
        cudaFuncSetAttribute(vq_main, cudaFuncAttributeMaxDynamicSharedMemorySize, DSMEM);
        attr_done = 1;
    }

    vq_normalize<<<MC, DIMS>>>(emb);
    vq_prep_x<<<NT / 8, 256>>>(x);              // 8 warps/block, 1 warp/row
    vq_main<<<NBLK, 256, DSMEM>>>(x, emb, out);
    vq_finalize<<<1, MC>>>(out);
}

// round 10
// speedup vs baseline: 1.1131x; 1.0947x over previous
#include <cuda_runtime.h>
#include <cuda_fp16.h>
#include <math.h>
#include <stdint.h>

// Problem constants
#define NT   65536      // N*T rows
#define DIMS 256        // D
#define MC   512        // M codes
#define BM   128        // rows per block of work
#define CN   128        // codes per chunk
#define BK   32         // k-chunk
#define NBLK (NT / BM)  // 512 work blocks
#define GRID 296        // persistent CTAs (2 per SM x 148)
#define PITCH 80        // smem row pitch bytes (conflict-free ldmatrix)
#define TILE (128 * PITCH)      // 10240 bytes per 128x32 fp16 tile
#define STAGE (4 * TILE)        // Ah, Al, Bh, Bl per stage
#define INV_SCALE 4.8828125e-4f // 1/2048

__device__ float g_e2[MC];
__device__ float g_s[MC];      // norm + 1e-4 per code
__device__ float g_q2[MC];     // ||raw emb row||^2
__device__ float g_x2[NT];
__device__ int   g_counts[MC];
__device__ int   g_ticket;
__device__ float g_loss_partial[NBLK];
// fp16 2-way splits; lo parts pre-scaled by 2048 (exact power of 2)
__device__ __align__(16) __half g_Eh[MC * DIMS];
__device__ __align__(16) __half g_El[MC * DIMS];
__device__ __align__(16) __half g_Xh[NT * DIMS];
__device__ __align__(16) __half g_Xl[NT * DIMS];

__device__ __forceinline__ uint32_t smem_u32(const void* p) {
    uint32_t a;
    asm("{ .reg .u64 t; cvta.to.shared.u64 t, %1; cvt.u32.u64 %0, t; }"
        : "=r"(a) : "l"(p));
    return a;
}
__device__ __forceinline__ uint32_t enc_f(float f) {
    uint32_t u = __float_as_uint(f);
    return (u & 0x80000000u) ? ~u : (u | 0x80000000u);
}
__device__ __forceinline__ float dec_f(uint32_t k) {
    uint32_t u = (k & 0x80000000u) ? (k & 0x7FFFFFFFu) : ~k;
    return __uint_as_float(u);
}

#define LDSM4(r0, r1, r2, r3, addr) \
    asm volatile("ldmatrix.sync.aligned.m8n8.x4.shared.b16 {%0,%1,%2,%3}, [%4];" \
                 : "=r"(r0), "=r"(r1), "=r"(r2), "=r"(r3) : "r"(addr))

#define MMA_F32(d, a0, a1, a2, a3, b0, b1) \
    asm volatile("mma.sync.aligned.m16n8k16.row.col.f32.f16.f16.f32 " \
                 "{%0,%1,%2,%3}, {%4,%5,%6,%7}, {%8,%9}, {%0,%1,%2,%3};" \
                 : "+f"((d)[0]), "+f"((d)[1]), "+f"((d)[2]), "+f"((d)[3]) \
                 : "r"(a0), "r"(a1), "r"(a2), "r"(a3), "r"(b0), "r"(b1))

#define MMA_F16(d, a0, a1, a2, a3, b0, b1) \
    asm volatile("mma.sync.aligned.m16n8k16.row.col.f16.f16.f16.f16 " \
                 "{%0,%1}, {%2,%3,%4,%5}, {%6,%7}, {%0,%1};" \
                 : "+r"((d)[0]), "+r"((d)[1]) \
                 : "r"(a0), "r"(a1), "r"(a2), "r"(a3), "r"(b0), "r"(b1))

#define CP_ASYNC16(dst, src) \
    asm volatile("cp.async.cg.shared.global [%0], [%1], 16;" \
                 :: "r"(dst), "l"(src) : "memory")
#define CP_COMMIT() asm volatile("cp.async.commit_group;" ::: "memory")
#define CP_WAIT(n)  asm volatile("cp.async.wait_group %0;" :: "n"(n) : "memory")

// ---------------------------------------------------------------------------
// Kernel 1: row-normalize codebook exactly like the reference; fp16 splits
// (lo scaled x2048); e2, s=norm+1e-4, q2; zero counters.
// ---------------------------------------------------------------------------
__global__ void vq_normalize(const float* __restrict__ emb) {
    __shared__ double red[8];
    __shared__ float bcast;
    int m = blockIdx.x;
    int t = threadIdx.x;       // 256 = D
    float v = emb[m * DIMS + t];

    double s = (double)v * (double)v;
    #pragma unroll
    for (int o = 16; o; o >>= 1) s += __shfl_xor_sync(0xffffffffu, s, o);
    if ((t & 31) == 0) red[t >> 5] = s;
    __syncthreads();
    if (t == 0) {
        double tot = 0.0;
        #pragma unroll
        for (int i = 0; i < 8; i++) tot += red[i];
        g_q2[m] = (float)tot;              // ||raw row||^2
        bcast = (float)sqrt(tot);
    }
    __syncthreads();
    float norm = bcast;
    float e = v / (norm + 1e-4f);          // IEEE rn division, matches ref

    __half h = __float2half_rn(e);
    float r1 = e - __half2float(h);
    g_Eh[m * DIMS + t] = h;
    g_El[m * DIMS + t] = __float2half_rn(r1 * 2048.0f);

    __syncthreads();
    double s2 = (double)e * (double)e;
    #pragma unroll
    for (int o = 16; o; o >>= 1) s2 += __shfl_xor_sync(0xffffffffu, s2, o);
    if ((t & 31) == 0) red[t >> 5] = s2;
    __syncthreads();
    if (t == 0) {
        double tot2 = 0.0;
        #pragma unroll
        for (int i = 0; i < 8; i++) tot2 += red[i];
        g_e2[m] = (float)tot2;
        g_s[m]  = norm + 1e-4f;
        g_counts[m] = 0;
    }
}

// ---------------------------------------------------------------------------
// Kernel 1b: per-row ||x||^2 (double, rounded once) + fp16 split of x
// (lo scaled x2048). One warp per row. Block 0 resets the work ticket.
// ---------------------------------------------------------------------------
__global__ void vq_prep_x(const float* __restrict__ x) {
    if (blockIdx.x == 0 && threadIdx.x == 0) g_ticket = 0;
    int warp = (blockIdx.x * blockDim.x + threadIdx.x) >> 5;
    int lane = threadIdx.x & 31;
    if (warp >= NT) return;
    const float* row = x + (size_t)warp * DIMS + lane * 8;
    float4 f0 = *(const float4*)row;
    float4 f1 = *(const float4*)(row + 4);
    float f[8] = {f0.x, f0.y, f0.z, f0.w, f1.x, f1.y, f1.z, f1.w};

    double s = 0.0;
    __half h[8], l[8];
    #pragma unroll
    for (int i = 0; i < 8; i++) {
        s += (double)f[i] * (double)f[i];
        h[i] = __float2half_rn(f[i]);
        float r = f[i] - __half2float(h[i]);
        l[i] = __float2half_rn(r * 2048.0f);
    }
    union { __half2 h2[4]; uint4 u; } P;
    size_t gi = (size_t)warp * DIMS + lane * 8;
    #pragma unroll
    for (int i = 0; i < 4; i++) P.h2[i] = __halves2half2(h[2*i], h[2*i+1]);
    *(uint4*)(g_Xh + gi) = P.u;
    #pragma unroll
    for (int i = 0; i < 4; i++) P.h2[i] = __halves2half2(l[2*i], l[2*i+1]);
    *(uint4*)(g_Xl + gi) = P.u;

    #pragma unroll
    for (int o = 16; o; o >>= 1) s += __shfl_xor_sync(0xffffffffu, s, o);
    if (lane == 0) g_x2[warp] = (float)s;
}

// ---------------------------------------------------------------------------
// Kernel 2: persistent main. R6 compute core (hh->fp32, hl+lh->fp16 acc,
// scaled), work-stealing over 512 row blocks, analytic commitment loss,
// warp-per-row gather. Reference-identical fp32 distance rounding.
// ---------------------------------------------------------------------------
__global__ void __launch_bounds__(256, 2)
vq_main(const float* __restrict__ x, const float* __restrict__ emb,
        float* __restrict__ out) {
    extern __shared__ char dsm[];           // 2 * STAGE = 81920 bytes
    __shared__ unsigned long long s_key[BM];
    __shared__ int   s_idx[BM];
    __shared__ float s_e2[MC];
    __shared__ float s_x2[BM];
    __shared__ float s_loss[BM];
    __shared__ float sred[8];
    __shared__ int   s_blk;

    const int tid  = threadIdx.x;
    const int lane = tid & 31;
    const int w    = tid >> 5;
    const int wr   = w >> 2;                 // 0..1 (row block of 64)
    const int wc   = w & 3;                  // 0..3 (col block of 32)

    s_e2[tid]       = g_e2[tid];
    s_e2[tid + 256] = g_e2[tid + 256];

    // cp.async task mapping: thread covers 2 chunks per tile
    const int c0 = tid, c1 = tid + 256;
    const int r_0 = c0 >> 2, cg0 = c0 & 3;
    const int r_1 = c1 >> 2, cg1 = c1 & 3;

    auto issue_stage = [&](int row0_, int ncc, int kcc, int buf) {
        uint32_t st = smem_u32(dsm) + buf * STAGE;
        size_t ka = (size_t)kcc * BK;
        const __half* srcAh = g_Xh + (size_t)row0_ * DIMS + ka;
        const __half* srcAl = g_Xl + (size_t)row0_ * DIMS + ka;
        const __half* srcBh = g_Eh + (size_t)(ncc * CN) * DIMS + ka;
        const __half* srcBl = g_El + (size_t)(ncc * CN) * DIMS + ka;
        uint32_t d0 = (uint32_t)(r_0 * PITCH + cg0 * 16);
        uint32_t d1 = (uint32_t)(r_1 * PITCH + cg1 * 16);
        size_t s0 = (size_t)r_0 * DIMS + cg0 * 8;
        size_t s1 = (size_t)r_1 * DIMS + cg1 * 8;
        CP_ASYNC16(st + d0,            srcAh + s0);
        CP_ASYNC16(st + d1,            srcAh + s1);
        CP_ASYNC16(st + TILE + d0,     srcAl + s0);
        CP_ASYNC16(st + TILE + d1,     srcAl + s1);
        CP_ASYNC16(st + 2 * TILE + d0, srcBh + s0);
        CP_ASYNC16(st + 2 * TILE + d1, srcBh + s1);
        CP_ASYNC16(st + 3 * TILE + d0, srcBl + s0);
        CP_ASYNC16(st + 3 * TILE + d1, srcBl + s1);
        CP_COMMIT();
    };

    for (;;) {
        if (tid == 0) s_blk = atomicAdd(&g_ticket, 1);
        __syncthreads();
        const int blk = s_blk;
        if (blk >= NBLK) break;
        const int row0 = blk * BM;

        if (tid < BM) {
            s_key[tid] = 0xFFFFFFFFFFFFFFFFULL;
            s_x2[tid] = g_x2[row0 + tid];
        }
        __syncthreads();

        issue_stage(row0, 0, 0, 0);

        #pragma unroll 1
        for (int nc = 0; nc < MC / CN; ++nc) {
            float    acc32[4][4][4];
            uint32_t acc16[4][4][2];
            #pragma unroll
            for (int i = 0; i < 4; i++)
                #pragma unroll
                for (int j = 0; j < 4; j++) {
                    #pragma unroll
                    for (int c = 0; c < 4; c++) acc32[i][j][c] = 0.f;
                    acc16[i][j][0] = 0u; acc16[i][j][1] = 0u;
                }

            #pragma unroll 1
            for (int kc = 0; kc < DIMS / BK; ++kc) {
                int step = nc * 8 + kc;
                int buf = step & 1;
                if (step < 31) {
                    int ns = step + 1;
                    issue_stage(row0, ns >> 3, ns & 7, ns & 1);
                    CP_WAIT(1);
                } else {
                    CP_WAIT(0);
                }
                __syncthreads();

                uint32_t st = smem_u32(dsm) + buf * STAGE;
                uint32_t aH = st, aL = st + TILE;
                uint32_t bH = st + 2 * TILE, bL = st + 3 * TILE;

                #pragma unroll
                for (int ks = 0; ks < 2; ++ks) {
                    uint32_t lsw = (lane & 15) * PITCH + ks * 32 + (lane >> 4) * 16;
                    uint32_t bOff0 = (wc * 32) * PITCH + lsw;
                    uint32_t bOff1 = (wc * 32 + 16) * PITCH + lsw;

                    uint32_t bh0, bh1, bh2, bh3, bh4, bh5, bh6, bh7;
                    LDSM4(bh0, bh1, bh2, bh3, bH + bOff0);
                    LDSM4(bh4, bh5, bh6, bh7, bH + bOff1);
                    uint32_t bl0, bl1, bl2, bl3, bl4, bl5, bl6, bl7;
                    LDSM4(bl0, bl1, bl2, bl3, bL + bOff0);
                    LDSM4(bl4, bl5, bl6, bl7, bL + bOff1);

                    #pragma unroll
                    for (int i = 0; i < 4; ++i) {
                        uint32_t a0, a1, a2, a3;
                        LDSM4(a0, a1, a2, a3, aH + (wr * 64 + i * 16) * PITCH + lsw);
                        MMA_F32(acc32[i][0], a0, a1, a2, a3, bh0, bh2);
                        MMA_F32(acc32[i][1], a0, a1, a2, a3, bh1, bh3);
                        MMA_F32(acc32[i][2], a0, a1, a2, a3, bh4, bh6);
                        MMA_F32(acc32[i][3], a0, a1, a2, a3, bh5, bh7);
                        MMA_F16(acc16[i][0], a0, a1, a2, a3, bl0, bl2);
                        MMA_F16(acc16[i][1], a0, a1, a2, a3, bl1, bl3);
                        MMA_F16(acc16[i][2], a0, a1, a2, a3, bl4, bl6);
                        MMA_F16(acc16[i][3], a0, a1, a2, a3, bl5, bl7);
                        LDSM4(a0, a1, a2, a3, aL + (wr * 64 + i * 16) * PITCH + lsw);
                        MMA_F16(acc16[i][0], a0, a1, a2, a3, bh0, bh2);
                        MMA_F16(acc16[i][1], a0, a1, a2, a3, bh1, bh3);
                        MMA_F16(acc16[i][2], a0, a1, a2, a3, bh4, bh6);
                        MMA_F16(acc16[i][3], a0, a1, a2, a3, bh5, bh7);
                    }
                }
                __syncthreads();
            }

            // ---- distance epilogue (reference rounding) + argmin
            #pragma unroll
            for (int i = 0; i < 4; ++i) {
                #pragma unroll
                for (int h = 0; h < 2; ++h) {
                    int row = wr * 64 + i * 16 + (lane >> 2) + 8 * h;
                    float x2v = s_x2[row];
                    unsigned long long kmin = 0xFFFFFFFFFFFFFFFFULL;
                    #pragma unroll
                    for (int j = 0; j < 4; ++j) {
                        __half2 sm = *(__half2*)&acc16[i][j][h];
                        float sv0 = __low2float(sm), sv1 = __high2float(sm);
                        #pragma unroll
                        for (int cl = 0; cl < 2; ++cl) {
                            int c = nc * CN + wc * 32 + j * 8 + 2 * (lane & 3) + cl;
                            float dot = __fmaf_rn(cl ? sv1 : sv0, INV_SCALE,
                                                  acc32[i][j][2 * h + cl]);
                            float base = __fadd_rn(s_e2[c], x2v);
                            float dval = __fmaf_rn(-2.0f, dot, base);
                            unsigned long long key =
                                ((unsigned long long)enc_f(dval) << 32) | (uint32_t)c;
                            if (key < kmin) kmin = key;
                        }
                    }
                    unsigned long long o1 = __shfl_xor_sync(0xffffffffu, kmin, 1);
                    if (o1 < kmin) kmin = o1;
                    unsigned long long o2 = __shfl_xor_sync(0xffffffffu, kmin, 2);
                    if (o2 < kmin) kmin = o2;
                    if ((lane & 3) == 0) atomicMin(&s_key[row], kmin);
                }
            }
            __syncthreads();
        }

        // ---- winners: counts + analytic commitment loss per row
        if (tid < BM) {
            unsigned long long key = s_key[tid];
            int bi = (int)(uint32_t)key;
            float dval = dec_f((uint32_t)(key >> 32));
            s_idx[tid] = bi;
            atomicAdd(&g_counts[bi], 1);
            float x2v = s_x2[tid];
            float base = __fadd_rn(s_e2[bi], x2v);
            float dot = 0.5f * (base - dval);          // x . e_norm (winner)
            // ||x - q||^2 = x2 - 2*(norm+1e-4)*dot + ||q||^2
            s_loss[tid] = x2v - 2.0f * g_s[bi] * dot + g_q2[bi];
        }
        __syncthreads();

        // ---- gather raw embedding rows -> out (warp per row, float4)
        #pragma unroll 2
        for (int r16 = 0; r16 < 16; ++r16) {
            int row = w * 16 + r16;
            int ci = s_idx[row];
            const float4* src = (const float4*)(emb + (size_t)ci * DIMS) + lane * 2;
            float4* dst = (float4*)(out + (size_t)(row0 + row) * DIMS) + lane * 2;
            float4 v0 = src[0], v1 = src[1];
            dst[0] = v0; dst[1] = v1;
        }

        // ---- deterministic loss reduce (warps 0-3 hold the 128 values)
        if (w < 4) {
            float lv = s_loss[tid];
            #pragma unroll
            for (int o = 16; o; o >>= 1) lv += __shfl_xor_sync(0xffffffffu, lv, o);
            if (lane == 0) sred[w] = lv;
        }
        __syncthreads();
        if (tid == 0)
            g_loss_partial[blk] = sred[0] + sred[1] + sred[2] + sred[3];
        __syncthreads();
    }
}

// ---------------------------------------------------------------------------
// Kernel 3: finalize scalars.
// ---------------------------------------------------------------------------
__global__ void vq_finalize(float* __restrict__ out) {
    __shared__ float sE[16], sL[16];
    int t = threadIdx.x;  // 512
    float p  = (float)g_counts[t] * (1.0f / 65536.0f);
    float ent = p * logf(p + 1e-10f);
    float lp  = g_loss_partial[t];
    #pragma unroll
    for (int o = 16; o; o >>= 1) {
        ent += __shfl_xor_sync(0xffffffffu, ent, o);
        lp  += __shfl_xor_sync(0xffffffffu, lp, o);
    }
    if ((t & 31) == 0) { sE[t >> 5] = ent; sL[t >> 5] = lp; }
    __syncthreads();
    if (t == 0) {
        float e = 0.f, l = 0.f;
        #pragma unroll
        for (int i = 0; i < 16; i++) { e += sE[i]; l += sL[i]; }
        out[(size_t)NT * DIMS]     = l * (1.0f / 16777216.0f);
        out[(size_t)NT * DIMS + 1] = expf(-e);
    }
}

extern "C" void kernel_launch(void* const* d_in, const int* in_sizes, int n_in,
                              void* d_out, int out_size) {
    const float* x   = (const float*)d_in[0];   // (16,4096,256)
    const float* emb = (const float*)d_in[1];   // (512,256)
    float* out = (float*)d_out;

    static int attr_done = 0;
    const int DSMEM = 2 * STAGE;                // 81920 bytes
    if (!attr_done) {
        cudaFuncSetAttribute(vq_main, cudaFuncAttributeMaxDynamicSharedMemorySize, DSMEM);
        attr_done = 1;
    }

    vq_normalize<<<MC, DIMS>>>(emb);
    vq_prep_x<<<NT / 8, 256>>>(x);              // 8 warps/block, 1 warp/row
    vq_main<<<GRID, 256, DSMEM>>>(x, emb, out);
    vq_finalize<<<1, MC>>>(out);
}

// round 11
// speedup vs baseline: 1.1740x; 1.0547x over previous
#include <cuda_runtime.h>
#include <cuda_fp16.h>
#include <math.h>
#include <stdint.h>

// Problem constants
#define NT   65536      // N*T rows
#define DIMS 256        // D
#define MC   512        // M codes
#define BM   128        // rows per work block
#define CN   128        // codes per chunk
#define BK   32         // k-chunk
#define NBLK (NT / BM)  // 512 row blocks
#define NITEM (NBLK * 4)        // work item = (row block, nc chunk)
#define GRID 296        // persistent CTAs (2 per SM x 148)
#define PITCH 80        // smem row pitch bytes (conflict-free ldmatrix)
#define TILE (128 * PITCH)      // 10240 bytes per 128x32 fp16 tile
#define STAGE (4 * TILE)        // Ah, Al, Bh, Bl per stage
#define INV_SCALE 4.8828125e-4f // 1/2048

__device__ float g_e2[MC];
__device__ float g_s[MC];      // norm + 1e-4 per code
__device__ float g_q2[MC];     // ||raw emb row||^2
__device__ float g_x2[NT];
__device__ int   g_counts[MC];
__device__ int   g_ticket;
__device__ unsigned long long g_key[NT];
__device__ float g_loss_partial[NBLK];
// fp16 2-way splits; lo parts pre-scaled by 2048 (exact power of 2)
__device__ __align__(16) __half g_Eh[MC * DIMS];
__device__ __align__(16) __half g_El[MC * DIMS];
__device__ __align__(16) __half g_Xh[NT * DIMS];
__device__ __align__(16) __half g_Xl[NT * DIMS];

__device__ __forceinline__ uint32_t smem_u32(const void* p) {
    uint32_t a;
    asm("{ .reg .u64 t; cvta.to.shared.u64 t, %1; cvt.u32.u64 %0, t; }"
        : "=r"(a) : "l"(p));
    return a;
}
__device__ __forceinline__ uint32_t enc_f(float f) {
    uint32_t u = __float_as_uint(f);
    return (u & 0x80000000u) ? ~u : (u | 0x80000000u);
}
__device__ __forceinline__ float dec_f(uint32_t k) {
    uint32_t u = (k & 0x80000000u) ? (k & 0x7FFFFFFFu) : ~k;
    return __uint_as_float(u);
}

#define LDSM4(r0, r1, r2, r3, addr) \
    asm volatile("ldmatrix.sync.aligned.m8n8.x4.shared.b16 {%0,%1,%2,%3}, [%4];" \
                 : "=r"(r0), "=r"(r1), "=r"(r2), "=r"(r3) : "r"(addr))

#define MMA_F32(d, a0, a1, a2, a3, b0, b1) \
    asm volatile("mma.sync.aligned.m16n8k16.row.col.f32.f16.f16.f32 " \
                 "{%0,%1,%2,%3}, {%4,%5,%6,%7}, {%8,%9}, {%0,%1,%2,%3};" \
                 : "+f"((d)[0]), "+f"((d)[1]), "+f"((d)[2]), "+f"((d)[3]) \
                 : "r"(a0), "r"(a1), "r"(a2), "r"(a3), "r"(b0), "r"(b1))

#define MMA_F16(d, a0, a1, a2, a3, b0, b1) \
    asm volatile("mma.sync.aligned.m16n8k16.row.col.f16.f16.f16.f16 " \
                 "{%0,%1}, {%2,%3,%4,%5}, {%6,%7}, {%0,%1};" \
                 : "+r"((d)[0]), "+r"((d)[1]) \
                 : "r"(a0), "r"(a1), "r"(a2), "r"(a3), "r"(b0), "r"(b1))

#define CP_ASYNC16(dst, src) \
    asm volatile("cp.async.cg.shared.global [%0], [%1], 16;" \
                 :: "r"(dst), "l"(src) : "memory")
#define CP_COMMIT() asm volatile("cp.async.commit_group;" ::: "memory")
#define CP_WAIT(n)  asm volatile("cp.async.wait_group %0;" :: "n"(n) : "memory")

// ---------------------------------------------------------------------------
// Kernel 1: row-normalize codebook exactly like the reference; fp16 splits
// (lo scaled x2048); e2, s = norm + 1e-4, q2; zero counters.
// ---------------------------------------------------------------------------
__global__ void vq_normalize(const float* __restrict__ emb) {
    __shared__ double red[8];
    __shared__ float bcast;
    int m = blockIdx.x;
    int t = threadIdx.x;       // 256 = D
    float v = emb[m * DIMS + t];

    double s = (double)v * (double)v;
    #pragma unroll
    for (int o = 16; o; o >>= 1) s += __shfl_xor_sync(0xffffffffu, s, o);
    if ((t & 31) == 0) red[t >> 5] = s;
    __syncthreads();
    if (t == 0) {
        double tot = 0.0;
        #pragma unroll
        for (int i = 0; i < 8; i++) tot += red[i];
        g_q2[m] = (float)tot;              // ||raw row||^2
        bcast = (float)sqrt(tot);
    }
    __syncthreads();
    float norm = bcast;
    float e = v / (norm + 1e-4f);          // IEEE rn division, matches ref

    __half h = __float2half_rn(e);
    float r1 = e - __half2float(h);
    g_Eh[m * DIMS + t] = h;
    g_El[m * DIMS + t] = __float2half_rn(r1 * 2048.0f);

    __syncthreads();
    double s2 = (double)e * (double)e;
    #pragma unroll
    for (int o = 16; o; o >>= 1) s2 += __shfl_xor_sync(0xffffffffu, s2, o);
    if ((t & 31) == 0) red[t >> 5] = s2;
    __syncthreads();
    if (t == 0) {
        double tot2 = 0.0;
        #pragma unroll
        for (int i = 0; i < 8; i++) tot2 += red[i];
        g_e2[m] = (float)tot2;
        g_s[m]  = norm + 1e-4f;
        g_counts[m] = 0;
    }
}

// ---------------------------------------------------------------------------
// Kernel 1b: per-row ||x||^2 (double, rounded once) + fp16 split of x
// (lo scaled x2048). One warp per row. Resets per-row keys and ticket.
// ---------------------------------------------------------------------------
__global__ void vq_prep_x(const float* __restrict__ x) {
    if (blockIdx.x == 0 && threadIdx.x == 0) g_ticket = 0;
    int warp = (blockIdx.x * blockDim.x + threadIdx.x) >> 5;
    int lane = threadIdx.x & 31;
    if (warp >= NT) return;
    const float* row = x + (size_t)warp * DIMS + lane * 8;
    float4 f0 = *(const float4*)row;
    float4 f1 = *(const float4*)(row + 4);
    float f[8] = {f0.x, f0.y, f0.z, f0.w, f1.x, f1.y, f1.z, f1.w};

    double s = 0.0;
    __half h[8], l[8];
    #pragma unroll
    for (int i = 0; i < 8; i++) {
        s += (double)f[i] * (double)f[i];
        h[i] = __float2half_rn(f[i]);
        float r = f[i] - __half2float(h[i]);
        l[i] = __float2half_rn(r * 2048.0f);
    }
    union { __half2 h2[4]; uint4 u; } P;
    size_t gi = (size_t)warp * DIMS + lane * 8;
    #pragma unroll
    for (int i = 0; i < 4; i++) P.h2[i] = __halves2half2(h[2*i], h[2*i+1]);
    *(uint4*)(g_Xh + gi) = P.u;
    #pragma unroll
    for (int i = 0; i < 4; i++) P.h2[i] = __halves2half2(l[2*i], l[2*i+1]);
    *(uint4*)(g_Xl + gi) = P.u;

    #pragma unroll
    for (int o = 16; o; o >>= 1) s += __shfl_xor_sync(0xffffffffu, s, o);
    if (lane == 0) {
        g_x2[warp] = (float)s;
        g_key[warp] = 0xFFFFFFFFFFFFFFFFULL;
    }
}

// ---------------------------------------------------------------------------
// Kernel 2: persistent MMA machine. Work item = (row block, nc chunk):
// 2048 items over 296 CTAs (98.8% schedule efficiency). hh->fp32 acc,
// hl+lh->fp16 acc (x2048). Per-row argmin merged via global atomicMin on
// packed (ref-rounded dval, idx) keys.
// ---------------------------------------------------------------------------
__global__ void __launch_bounds__(256, 2)
vq_main() {
    extern __shared__ char dsm[];           // 2 * STAGE = 81920 bytes
    __shared__ float s_e2[MC];
    __shared__ float s_x2[BM];
    __shared__ int   s_item;

    const int tid  = threadIdx.x;
    const int lane = tid & 31;
    const int w    = tid >> 5;
    const int wr   = w >> 2;                 // 0..1 (row block of 64)
    const int wc   = w & 3;                  // 0..3 (col block of 32)

    s_e2[tid]       = g_e2[tid];
    s_e2[tid + 256] = g_e2[tid + 256];

    // cp.async task mapping: thread covers 2 chunks per tile
    const int c0 = tid, c1 = tid + 256;
    const int r_0 = c0 >> 2, cg0 = c0 & 3;
    const int r_1 = c1 >> 2, cg1 = c1 & 3;

    auto issue_stage = [&](int row0_, int ncc, int kcc, int buf) {
        uint32_t st = smem_u32(dsm) + buf * STAGE;
        size_t ka = (size_t)kcc * BK;
        const __half* srcAh = g_Xh + (size_t)row0_ * DIMS + ka;
        const __half* srcAl = g_Xl + (size_t)row0_ * DIMS + ka;
        const __half* srcBh = g_Eh + (size_t)(ncc * CN) * DIMS + ka;
        const __half* srcBl = g_El + (size_t)(ncc * CN) * DIMS + ka;
        uint32_t d0 = (uint32_t)(r_0 * PITCH + cg0 * 16);
        uint32_t d1 = (uint32_t)(r_1 * PITCH + cg1 * 16);
        size_t s0 = (size_t)r_0 * DIMS + cg0 * 8;
        size_t s1 = (size_t)r_1 * DIMS + cg1 * 8;
        CP_ASYNC16(st + d0,            srcAh + s0);
        CP_ASYNC16(st + d1,            srcAh + s1);
        CP_ASYNC16(st + TILE + d0,     srcAl + s0);
        CP_ASYNC16(st + TILE + d1,     srcAl + s1);
        CP_ASYNC16(st + 2 * TILE + d0, srcBh + s0);
        CP_ASYNC16(st + 2 * TILE + d1, srcBh + s1);
        CP_ASYNC16(st + 3 * TILE + d0, srcBl + s0);
        CP_ASYNC16(st + 3 * TILE + d1, srcBl + s1);
        CP_COMMIT();
    };

    for (;;) {
        if (tid == 0) s_item = atomicAdd(&g_ticket, 1);
        __syncthreads();                     // also guards smem stage reuse
        const int item = s_item;
        if (item >= NITEM) break;
        const int blk = item >> 2;
        const int nc  = item & 3;
        const int row0 = blk * BM;

        if (tid < BM) s_x2[tid] = g_x2[row0 + tid];

        issue_stage(row0, nc, 0, 0);

        float    acc32[4][4][4];
        uint32_t acc16[4][4][2];
        #pragma unroll
        for (int i = 0; i < 4; i++)
            #pragma unroll
            for (int j = 0; j < 4; j++) {
                #pragma unroll
                for (int c = 0; c < 4; c++) acc32[i][j][c] = 0.f;
                acc16[i][j][0] = 0u; acc16[i][j][1] = 0u;
            }

        #pragma unroll 1
        for (int kc = 0; kc < DIMS / BK; ++kc) {
            int buf = kc & 1;
            if (kc < 7) {
                issue_stage(row0, nc, kc + 1, buf ^ 1);
                CP_WAIT(1);
            } else {
                CP_WAIT(0);
            }
            __syncthreads();

            uint32_t st = smem_u32(dsm) + buf * STAGE;
            uint32_t aH = st, aL = st + TILE;
            uint32_t bH = st + 2 * TILE, bL = st + 3 * TILE;

            #pragma unroll
            for (int ks = 0; ks < 2; ++ks) {
                uint32_t lsw = (lane & 15) * PITCH + ks * 32 + (lane >> 4) * 16;
                uint32_t bOff0 = (wc * 32) * PITCH + lsw;
                uint32_t bOff1 = (wc * 32 + 16) * PITCH + lsw;

                uint32_t bh0, bh1, bh2, bh3, bh4, bh5, bh6, bh7;
                LDSM4(bh0, bh1, bh2, bh3, bH + bOff0);
                LDSM4(bh4, bh5, bh6, bh7, bH + bOff1);
                uint32_t bl0, bl1, bl2, bl3, bl4, bl5, bl6, bl7;
                LDSM4(bl0, bl1, bl2, bl3, bL + bOff0);
                LDSM4(bl4, bl5, bl6, bl7, bL + bOff1);

                #pragma unroll
                for (int i = 0; i < 4; ++i) {
                    uint32_t a0, a1, a2, a3;
                    LDSM4(a0, a1, a2, a3, aH + (wr * 64 + i * 16) * PITCH + lsw);
                    MMA_F32(acc32[i][0], a0, a1, a2, a3, bh0, bh2);
                    MMA_F32(acc32[i][1], a0, a1, a2, a3, bh1, bh3);
                    MMA_F32(acc32[i][2], a0, a1, a2, a3, bh4, bh6);
                    MMA_F32(acc32[i][3], a0, a1, a2, a3, bh5, bh7);
                    MMA_F16(acc16[i][0], a0, a1, a2, a3, bl0, bl2);
                    MMA_F16(acc16[i][1], a0, a1, a2, a3, bl1, bl3);
                    MMA_F16(acc16[i][2], a0, a1, a2, a3, bl4, bl6);
                    MMA_F16(acc16[i][3], a0, a1, a2, a3, bl5, bl7);
                    LDSM4(a0, a1, a2, a3, aL + (wr * 64 + i * 16) * PITCH + lsw);
                    MMA_F16(acc16[i][0], a0, a1, a2, a3, bh0, bh2);
                    MMA_F16(acc16[i][1], a0, a1, a2, a3, bh1, bh3);
                    MMA_F16(acc16[i][2], a0, a1, a2, a3, bh4, bh6);
                    MMA_F16(acc16[i][3], a0, a1, a2, a3, bh5, bh7);
                }
            }
            __syncthreads();
        }

        // ---- distance epilogue (reference rounding) + global argmin merge
        #pragma unroll
        for (int i = 0; i < 4; ++i) {
            #pragma unroll
            for (int h = 0; h < 2; ++h) {
                int row = wr * 64 + i * 16 + (lane >> 2) + 8 * h;
                float x2v = s_x2[row];
                unsigned long long kmin = 0xFFFFFFFFFFFFFFFFULL;
                #pragma unroll
                for (int j = 0; j < 4; ++j) {
                    __half2 sm = *(__half2*)&acc16[i][j][h];
                    float sv0 = __low2float(sm), sv1 = __high2float(sm);
                    #pragma unroll
                    for (int cl = 0; cl < 2; ++cl) {
                        int c = nc * CN + wc * 32 + j * 8 + 2 * (lane & 3) + cl;
                        float dot = __fmaf_rn(cl ? sv1 : sv0, INV_SCALE,
                                              acc32[i][j][2 * h + cl]);
                        float base = __fadd_rn(s_e2[c], x2v);
                        float dval = __fmaf_rn(-2.0f, dot, base);
                        unsigned long long key =
                            ((unsigned long long)enc_f(dval) << 32) | (uint32_t)c;
                        if (key < kmin) kmin = key;
                    }
                }
                unsigned long long o1 = __shfl_xor_sync(0xffffffffu, kmin, 1);
                if (o1 < kmin) kmin = o1;
                unsigned long long o2 = __shfl_xor_sync(0xffffffffu, kmin, 2);
                if (o2 < kmin) kmin = o2;
                if ((lane & 3) == 0) atomicMin(&g_key[row0 + row], kmin);
            }
        }
    }
}

// ---------------------------------------------------------------------------
// Kernel 2b: decode winners: counts, analytic commitment loss, gather
// raw embedding rows to out (warp per row, float4).
// ---------------------------------------------------------------------------
__global__ void __launch_bounds__(256, 2)
vq_gather(const float* __restrict__ emb, float* __restrict__ out) {
    __shared__ int   s_idx[BM];
    __shared__ float s_loss[BM];
    __shared__ float sred[8];
    const int tid  = threadIdx.x;
    const int lane = tid & 31;
    const int w    = tid >> 5;
    const int blk  = blockIdx.x;
    const int row0 = blk * BM;

    if (tid < BM) {
        unsigned long long key = g_key[row0 + tid];
        int bi = (int)(uint32_t)key;
        float dval = dec_f((uint32_t)(key >> 32));
        s_idx[tid] = bi;
        atomicAdd(&g_counts[bi], 1);
        float x2v = g_x2[row0 + tid];
        float base = __fadd_rn(g_e2[bi], x2v);
        float dot = 0.5f * (base - dval);          // x . e_norm (winner)
        s_loss[tid] = x2v - 2.0f * g_s[bi] * dot + g_q2[bi];
    }
    __syncthreads();

    #pragma unroll 2
    for (int r16 = 0; r16 < 16; ++r16) {
        int row = w * 16 + r16;
        int ci = s_idx[row];
        const float4* src = (const float4*)(emb + (size_t)ci * DIMS) + lane * 2;
        float4* dst = (float4*)(out + (size_t)(row0 + row) * DIMS) + lane * 2;
        float4 v0 = src[0], v1 = src[1];
        dst[0] = v0; dst[1] = v1;
    }

    if (w < 4) {
        float lv = s_loss[tid];
        #pragma unroll
        for (int o = 16; o; o >>= 1) lv += __shfl_xor_sync(0xffffffffu, lv, o);
        if (lane == 0) sred[w] = lv;
    }
    __syncthreads();
    if (tid == 0)
        g_loss_partial[blk] = sred[0] + sred[1] + sred[2] + sred[3];
}

// ---------------------------------------------------------------------------
// Kernel 3: finalize scalars.
// ---------------------------------------------------------------------------
__global__ void vq_finalize(float* __restrict__ out) {
    __shared__ float sE[16], sL[16];
    int t = threadIdx.x;  // 512
    float p  = (float)g_counts[t] * (1.0f / 65536.0f);
    float ent = p * logf(p + 1e-10f);
    float lp  = g_loss_partial[t];
    #pragma unroll
    for (int o = 16; o; o >>= 1) {
        ent += __shfl_xor_sync(0xffffffffu, ent, o);
        lp  += __shfl_xor_sync(0xffffffffu, lp, o);
    }
    if ((t & 31) == 0) { sE[t >> 5] = ent; sL[t >> 5] = lp; }
    __syncthreads();
    if (t == 0) {
        float e = 0.f, l = 0.f;
        #pragma unroll
        for (int i = 0; i < 16; i++) { e += sE[i]; l += sL[i]; }
        out[(size_t)NT * DIMS]     = l * (1.0f / 16777216.0f);
        out[(size_t)NT * DIMS + 1] = expf(-e);
    }
}

extern "C" void kernel_launch(void* const* d_in, const int* in_sizes, int n_in,
                              void* d_out, int out_size) {
    const float* x   = (const float*)d_in[0];   // (16,4096,256)
    const float* emb = (const float*)d_in[1];   // (512,256)
    float* out = (float*)d_out;

    static int attr_done = 0;
    const int DSMEM = 2 * STAGE;                // 81920 bytes
    if (!attr_done) {
        cudaFuncSetAttribute(vq_main, cudaFuncAttributeMaxDynamicSharedMemorySize, DSMEM);
        attr_done = 1;
    }

    vq_normalize<<<MC, DIMS>>>(emb);
    vq_prep_x<<<NT / 8, 256>>>(x);              // 8 warps/block, 1 warp/row
    vq_main<<<GRID, 256, DSMEM>>>();
    vq_gather<<<NBLK, 256>>>(emb, out);
    vq_finalize<<<1, MC>>>(out);
}

// round 12
// speedup vs baseline: 1.2142x; 1.0342x over previous
#include <cuda_runtime.h>
#include <cuda_fp16.h>
#include <math.h>
#include <stdint.h>

// Problem constants
#define NT   65536      // N*T rows
#define DIMS 256        // D
#define MC   512        // M codes
#define BM   128        // rows per work block
#define CN   128        // codes per chunk
#define BK   32         // k-chunk
#define NBLK (NT / BM)  // 512 row blocks
#define NITEM (NBLK * 4)        // work item = (row block, nc chunk)
#define GRID 296        // persistent CTAs (2 per SM x 148)
#define PITCH 80        // smem row pitch bytes (conflict-free ldmatrix)
#define TILE (128 * PITCH)      // 10240 bytes per 128x32 fp16 tile
#define STAGE (4 * TILE)        // Ah, Al, Bh, Bl per stage
#define INV_SCALE 4.8828125e-4f // 1/2048

__device__ float g_e2[MC];
__device__ float g_s[MC];      // norm + 1e-4 per code
__device__ float g_q2[MC];     // ||raw emb row||^2
__device__ float g_x2[NT];
__device__ int   g_counts[MC];
__device__ int   g_ticket;
__device__ int   g_done[NBLK];
__device__ unsigned long long g_key[NT];
__device__ float g_loss_partial[NBLK];
// fp16 2-way splits; lo parts pre-scaled by 2048 (exact power of 2)
__device__ __align__(16) __half g_Eh[MC * DIMS];
__device__ __align__(16) __half g_El[MC * DIMS];
__device__ __align__(16) __half g_Xh[NT * DIMS];
__device__ __align__(16) __half g_Xl[NT * DIMS];

__device__ __forceinline__ uint32_t smem_u32(const void* p) {
    uint32_t a;
    asm("{ .reg .u64 t; cvta.to.shared.u64 t, %1; cvt.u32.u64 %0, t; }"
        : "=r"(a) : "l"(p));
    return a;
}
__device__ __forceinline__ uint32_t enc_f(float f) {
    uint32_t u = __float_as_uint(f);
    return (u & 0x80000000u) ? ~u : (u | 0x80000000u);
}
__device__ __forceinline__ float dec_f(uint32_t k) {
    uint32_t u = (k & 0x80000000u) ? (k & 0x7FFFFFFFu) : ~k;
    return __uint_as_float(u);
}
__device__ __forceinline__ unsigned long long ldcg_u64(const unsigned long long* p) {
    unsigned long long v;
    asm volatile("ld.global.cg.u64 %0, [%1];" : "=l"(v) : "l"(p));
    return v;
}

#define LDSM4(r0, r1, r2, r3, addr) \
    asm volatile("ldmatrix.sync.aligned.m8n8.x4.shared.b16 {%0,%1,%2,%3}, [%4];" \
                 : "=r"(r0), "=r"(r1), "=r"(r2), "=r"(r3) : "r"(addr))

#define MMA_F32(d, a0, a1, a2, a3, b0, b1) \
    asm volatile("mma.sync.aligned.m16n8k16.row.col.f32.f16.f16.f32 " \
                 "{%0,%1,%2,%3}, {%4,%5,%6,%7}, {%8,%9}, {%0,%1,%2,%3};" \
                 : "+f"((d)[0]), "+f"((d)[1]), "+f"((d)[2]), "+f"((d)[3]) \
                 : "r"(a0), "r"(a1), "r"(a2), "r"(a3), "r"(b0), "r"(b1))

#define MMA_F16(d, a0, a1, a2, a3, b0, b1) \
    asm volatile("mma.sync.aligned.m16n8k16.row.col.f16.f16.f16.f16 " \
                 "{%0,%1}, {%2,%3,%4,%5}, {%6,%7}, {%0,%1};" \
                 : "+r"((d)[0]), "+r"((d)[1]) \
                 : "r"(a0), "r"(a1), "r"(a2), "r"(a3), "r"(b0), "r"(b1))

#define CP_ASYNC16(dst, src) \
    asm volatile("cp.async.cg.shared.global [%0], [%1], 16;" \
                 :: "r"(dst), "l"(src) : "memory")
#define CP_COMMIT() asm volatile("cp.async.commit_group;" ::: "memory")
#define CP_WAIT(n)  asm volatile("cp.async.wait_group %0;" :: "n"(n) : "memory")

// ---------------------------------------------------------------------------
// Kernel 1: row-normalize codebook exactly like the reference; fp16 splits
// (lo scaled x2048); e2, s = norm + 1e-4, q2; zero counters.
// ---------------------------------------------------------------------------
__global__ void vq_normalize(const float* __restrict__ emb) {
    __shared__ double red[8];
    __shared__ float bcast;
    int m = blockIdx.x;
    int t = threadIdx.x;       // 256 = D
    float v = emb[m * DIMS + t];

    double s = (double)v * (double)v;
    #pragma unroll
    for (int o = 16; o; o >>= 1) s += __shfl_xor_sync(0xffffffffu, s, o);
    if ((t & 31) == 0) red[t >> 5] = s;
    __syncthreads();
    if (t == 0) {
        double tot = 0.0;
        #pragma unroll
        for (int i = 0; i < 8; i++) tot += red[i];
        g_q2[m] = (float)tot;              // ||raw row||^2
        bcast = (float)sqrt(tot);
    }
    __syncthreads();
    float norm = bcast;
    float e = v / (norm + 1e-4f);          // IEEE rn division, matches ref

    __half h = __float2half_rn(e);
    float r1 = e - __half2float(h);
    g_Eh[m * DIMS + t] = h;
    g_El[m * DIMS + t] = __float2half_rn(r1 * 2048.0f);

    __syncthreads();
    double s2 = (double)e * (double)e;
    #pragma unroll
    for (int o = 16; o; o >>= 1) s2 += __shfl_xor_sync(0xffffffffu, s2, o);
    if ((t & 31) == 0) red[t >> 5] = s2;
    __syncthreads();
    if (t == 0) {
        double tot2 = 0.0;
        #pragma unroll
        for (int i = 0; i < 8; i++) tot2 += red[i];
        g_e2[m] = (float)tot2;
        g_s[m]  = norm + 1e-4f;
        g_counts[m] = 0;
    }
}

// ---------------------------------------------------------------------------
// Kernel 1b: per-row ||x||^2 (double, rounded once) + fp16 split of x
// (lo scaled x2048). One warp per row. Resets keys, ticket, done counters.
// ---------------------------------------------------------------------------
__global__ void vq_prep_x(const float* __restrict__ x) {
    int gtid = blockIdx.x * blockDim.x + threadIdx.x;
    if (gtid == 0) g_ticket = 0;
    if (gtid < NBLK) g_done[gtid] = 0;
    int warp = gtid >> 5;
    int lane = threadIdx.x & 31;
    if (warp >= NT) return;
    const float* row = x + (size_t)warp * DIMS + lane * 8;
    float4 f0 = *(const float4*)row;
    float4 f1 = *(const float4*)(row + 4);
    float f[8] = {f0.x, f0.y, f0.z, f0.w, f1.x, f1.y, f1.z, f1.w};

    double s = 0.0;
    __half h[8], l[8];
    #pragma unroll
    for (int i = 0; i < 8; i++) {
        s += (double)f[i] * (double)f[i];
        h[i] = __float2half_rn(f[i]);
        float r = f[i] - __half2float(h[i]);
        l[i] = __float2half_rn(r * 2048.0f);
    }
    union { __half2 h2[4]; uint4 u; } P;
    size_t gi = (size_t)warp * DIMS + lane * 8;
    #pragma unroll
    for (int i = 0; i < 4; i++) P.h2[i] = __halves2half2(h[2*i], h[2*i+1]);
    *(uint4*)(g_Xh + gi) = P.u;
    #pragma unroll
    for (int i = 0; i < 4; i++) P.h2[i] = __halves2half2(l[2*i], l[2*i+1]);
    *(uint4*)(g_Xl + gi) = P.u;

    #pragma unroll
    for (int o = 16; o; o >>= 1) s += __shfl_xor_sync(0xffffffffu, s, o);
    if (lane == 0) {
        g_x2[warp] = (float)s;
        g_key[warp] = 0xFFFFFFFFFFFFFFFFULL;
    }
}

// ---------------------------------------------------------------------------
// Kernel 2: persistent MMA machine + fused gather. Work item = (row block,
// nc chunk). hh->fp32 acc, hl+lh->fp16 acc (x2048). Per-row argmin merged
// via global atomicMin on packed (ref-rounded dval, idx) keys. The CTA
// completing a block's 4th item decodes winners, counts, computes analytic
// commitment loss, and gathers embedding rows to out (overlapped with the
// remaining MMA work of other CTAs).
// ---------------------------------------------------------------------------
__global__ void __launch_bounds__(256, 2)
vq_main(const float* __restrict__ emb, float* __restrict__ out) {
    extern __shared__ char dsm[];           // 2 * STAGE = 81920 bytes
    __shared__ float s_e2[MC];
    __shared__ float s_x2[BM];
    __shared__ int   s_idx[BM];
    __shared__ float s_loss[BM];
    __shared__ float sred[8];
    __shared__ int   s_item;
    __shared__ int   s_do;

    const int tid  = threadIdx.x;
    const int lane = tid & 31;
    const int w    = tid >> 5;
    const int wr   = w >> 2;                 // 0..1 (row block of 64)
    const int wc   = w & 3;                  // 0..3 (col block of 32)

    s_e2[tid]       = g_e2[tid];
    s_e2[tid + 256] = g_e2[tid + 256];

    // cp.async task mapping: thread covers 2 chunks per tile
    const int c0 = tid, c1 = tid + 256;
    const int r_0 = c0 >> 2, cg0 = c0 & 3;
    const int r_1 = c1 >> 2, cg1 = c1 & 3;

    auto issue_stage = [&](int row0_, int ncc, int kcc, int buf) {
        uint32_t st = smem_u32(dsm) + buf * STAGE;
        size_t ka = (size_t)kcc * BK;
        const __half* srcAh = g_Xh + (size_t)row0_ * DIMS + ka;
        const __half* srcAl = g_Xl + (size_t)row0_ * DIMS + ka;
        const __half* srcBh = g_Eh + (size_t)(ncc * CN) * DIMS + ka;
        const __half* srcBl = g_El + (size_t)(ncc * CN) * DIMS + ka;
        uint32_t d0 = (uint32_t)(r_0 * PITCH + cg0 * 16);
        uint32_t d1 = (uint32_t)(r_1 * PITCH + cg1 * 16);
        size_t s0 = (size_t)r_0 * DIMS + cg0 * 8;
        size_t s1 = (size_t)r_1 * DIMS + cg1 * 8;
        CP_ASYNC16(st + d0,            srcAh + s0);
        CP_ASYNC16(st + d1,            srcAh + s1);
        CP_ASYNC16(st + TILE + d0,     srcAl + s0);
        CP_ASYNC16(st + TILE + d1,     srcAl + s1);
        CP_ASYNC16(st + 2 * TILE + d0, srcBh + s0);
        CP_ASYNC16(st + 2 * TILE + d1, srcBh + s1);
        CP_ASYNC16(st + 3 * TILE + d0, srcBl + s0);
        CP_ASYNC16(st + 3 * TILE + d1, srcBl + s1);
        CP_COMMIT();
    };

    for (;;) {
        if (tid == 0) s_item = atomicAdd(&g_ticket, 1);
        __syncthreads();                     // also guards smem stage reuse
        const int item = s_item;
        if (item >= NITEM) break;
        const int blk = item >> 2;
        const int nc  = item & 3;
        const int row0 = blk * BM;

        if (tid < BM) s_x2[tid] = g_x2[row0 + tid];

        issue_stage(row0, nc, 0, 0);

        float    acc32[4][4][4];
        uint32_t acc16[4][4][2];
        #pragma unroll
        for (int i = 0; i < 4; i++)
            #pragma unroll
            for (int j = 0; j < 4; j++) {
                #pragma unroll
                for (int c = 0; c < 4; c++) acc32[i][j][c] = 0.f;
                acc16[i][j][0] = 0u; acc16[i][j][1] = 0u;
            }

        #pragma unroll 1
        for (int kc = 0; kc < DIMS / BK; ++kc) {
            int buf = kc & 1;
            if (kc < 7) {
                issue_stage(row0, nc, kc + 1, buf ^ 1);
                CP_WAIT(1);
            } else {
                CP_WAIT(0);
            }
            __syncthreads();

            uint32_t st = smem_u32(dsm) + buf * STAGE;
            uint32_t aH = st, aL = st + TILE;
            uint32_t bH = st + 2 * TILE, bL = st + 3 * TILE;

            #pragma unroll
            for (int ks = 0; ks < 2; ++ks) {
                uint32_t lsw = (lane & 15) * PITCH + ks * 32 + (lane >> 4) * 16;
                uint32_t bOff0 = (wc * 32) * PITCH + lsw;
                uint32_t bOff1 = (wc * 32 + 16) * PITCH + lsw;

                uint32_t bh0, bh1, bh2, bh3, bh4, bh5, bh6, bh7;
                LDSM4(bh0, bh1, bh2, bh3, bH + bOff0);
                LDSM4(bh4, bh5, bh6, bh7, bH + bOff1);
                uint32_t bl0, bl1, bl2, bl3, bl4, bl5, bl6, bl7;
                LDSM4(bl0, bl1, bl2, bl3, bL + bOff0);
                LDSM4(bl4, bl5, bl6, bl7, bL + bOff1);

                #pragma unroll
                for (int i = 0; i < 4; ++i) {
                    uint32_t a0, a1, a2, a3;
                    LDSM4(a0, a1, a2, a3, aH + (wr * 64 + i * 16) * PITCH + lsw);
                    MMA_F32(acc32[i][0], a0, a1, a2, a3, bh0, bh2);
                    MMA_F32(acc32[i][1], a0, a1, a2, a3, bh1, bh3);
                    MMA_F32(acc32[i][2], a0, a1, a2, a3, bh4, bh6);
                    MMA_F32(acc32[i][3], a0, a1, a2, a3, bh5, bh7);
                    MMA_F16(acc16[i][0], a0, a1, a2, a3, bl0, bl2);
                    MMA_F16(acc16[i][1], a0, a1, a2, a3, bl1, bl3);
                    MMA_F16(acc16[i][2], a0, a1, a2, a3, bl4, bl6);
                    MMA_F16(acc16[i][3], a0, a1, a2, a3, bl5, bl7);
                    LDSM4(a0, a1, a2, a3, aL + (wr * 64 + i * 16) * PITCH + lsw);
                    MMA_F16(acc16[i][0], a0, a1, a2, a3, bh0, bh2);
                    MMA_F16(acc16[i][1], a0, a1, a2, a3, bh1, bh3);
                    MMA_F16(acc16[i][2], a0, a1, a2, a3, bh4, bh6);
                    MMA_F16(acc16[i][3], a0, a1, a2, a3, bh5, bh7);
                }
            }
            __syncthreads();
        }

        // ---- distance epilogue (reference rounding) + global argmin merge
        #pragma unroll
        for (int i = 0; i < 4; ++i) {
            #pragma unroll
            for (int h = 0; h < 2; ++h) {
                int row = wr * 64 + i * 16 + (lane >> 2) + 8 * h;
                float x2v = s_x2[row];
                unsigned long long kmin = 0xFFFFFFFFFFFFFFFFULL;
                #pragma unroll
                for (int j = 0; j < 4; ++j) {
                    __half2 sm = *(__half2*)&acc16[i][j][h];
                    float sv0 = __low2float(sm), sv1 = __high2float(sm);
                    #pragma unroll
                    for (int cl = 0; cl < 2; ++cl) {
                        int c = nc * CN + wc * 32 + j * 8 + 2 * (lane & 3) + cl;
                        float dot = __fmaf_rn(cl ? sv1 : sv0, INV_SCALE,
                                              acc32[i][j][2 * h + cl]);
                        float base = __fadd_rn(s_e2[c], x2v);
                        float dval = __fmaf_rn(-2.0f, dot, base);
                        unsigned long long key =
                            ((unsigned long long)enc_f(dval) << 32) | (uint32_t)c;
                        if (key < kmin) kmin = key;
                    }
                }
                unsigned long long o1 = __shfl_xor_sync(0xffffffffu, kmin, 1);
                if (o1 < kmin) kmin = o1;
                unsigned long long o2 = __shfl_xor_sync(0xffffffffu, kmin, 2);
                if (o2 < kmin) kmin = o2;
                if ((lane & 3) == 0) atomicMin(&g_key[row0 + row], kmin);
            }
        }

        // ---- completion protocol (threadfence-reduction pattern):
        // all threads fence, barrier, then tid0 bumps the block counter.
        __threadfence();
        __syncthreads();
        if (tid == 0) s_do = (atomicAdd(&g_done[blk], 1) == 3);
        __syncthreads();

        if (s_do) {
            // This CTA completed the block's last chunk: decode winners,
            // count, analytic commitment loss, gather embedding rows.
            if (tid < BM) {
                unsigned long long key = ldcg_u64(g_key + row0 + tid);
                int bi = (int)(uint32_t)key;
                float dval = dec_f((uint32_t)(key >> 32));
                s_idx[tid] = bi;
                atomicAdd(&g_counts[bi], 1);
                float x2v = s_x2[tid];
                float base = __fadd_rn(s_e2[bi], x2v);
                float dot = 0.5f * (base - dval);      // x . e_norm (winner)
                s_loss[tid] = x2v - 2.0f * g_s[bi] * dot + g_q2[bi];
            }
            __syncthreads();

            #pragma unroll 2
            for (int r16 = 0; r16 < 16; ++r16) {
                int row = w * 16 + r16;
                int ci = s_idx[row];
                const float4* src = (const float4*)(emb + (size_t)ci * DIMS) + lane * 2;
                float4* dst = (float4*)(out + (size_t)(row0 + row) * DIMS) + lane * 2;
                float4 v0 = src[0], v1 = src[1];
                dst[0] = v0; dst[1] = v1;
            }

            if (w < 4) {
                float lv = s_loss[tid];
                #pragma unroll
                for (int o = 16; o; o >>= 1) lv += __shfl_xor_sync(0xffffffffu, lv, o);
                if (lane == 0) sred[w] = lv;
            }
            __syncthreads();
            if (tid == 0)
                g_loss_partial[blk] = sred[0] + sred[1] + sred[2] + sred[3];
        }
    }
}

// ---------------------------------------------------------------------------
// Kernel 3: finalize scalars.
// ---------------------------------------------------------------------------
__global__ void vq_finalize(float* __restrict__ out) {
    __shared__ float sE[16], sL[16];
    int t = threadIdx.x;  // 512
    float p  = (float)g_counts[t] * (1.0f / 65536.0f);
    float ent = p * logf(p + 1e-10f);
    float lp  = g_loss_partial[t];
    #pragma unroll
    for (int o = 16; o; o >>= 1) {
        ent += __shfl_xor_sync(0xffffffffu, ent, o);
        lp  += __shfl_xor_sync(0xffffffffu, lp, o);
    }
    if ((t & 31) == 0) { sE[t >> 5] = ent; sL[t >> 5] = lp; }
    __syncthreads();
    if (t == 0) {
        float e = 0.f, l = 0.f;
        #pragma unroll
        for (int i = 0; i < 16; i++) { e += sE[i]; l += sL[i]; }
        out[(size_t)NT * DIMS]     = l * (1.0f / 16777216.0f);
        out[(size_t)NT * DIMS + 1] = expf(-e);
    }
}

extern "C" void kernel_launch(void* const* d_in, const int* in_sizes, int n_in,
                              void* d_out, int out_size) {
    const float* x   = (const float*)d_in[0];   // (16,4096,256)
    const float* emb = (const float*)d_in[1];   // (512,256)
    float* out = (float*)d_out;

    static int attr_done = 0;
    const int DSMEM = 2 * STAGE;                // 81920 bytes
    if (!attr_done) {
        cudaFuncSetAttribute(vq_main, cudaFuncAttributeMaxDynamicSharedMemorySize, DSMEM);
        attr_done = 1;
    }

    vq_normalize<<<MC, DIMS>>>(emb);
    vq_prep_x<<<NT / 8, 256>>>(x);              // 8 warps/block, 1 warp/row
    vq_main<<<GRID, 256, DSMEM>>>(emb, out);
    vq_finalize<<<1, MC>>>(out);
}